// round 1
// baseline (speedup 1.0000x reference)
#include <cuda_runtime.h>
#include <cstdint>
#include <math.h>

namespace {
constexpr int kB   = 4;
constexpr int kLq  = 512;
constexpr int kLkv = 2048;
constexpr int kDim = 1024;
constexpr int kH   = 16;
constexpr int kHd  = 64;
constexpr int kMlp = 4096;
constexpr int kNQ  = kB * kLq;    // 2048 query rows
constexpr int kNKV = kB * kLkv;   // 8192 kv rows
}

// Single scratch arena: 40M floats = 160 MB (static device allocation, no cudaMalloc)
__device__ float g_scratch[40u * 1024u * 1024u];

// ---------------------------------------------------------------------------
// LayerNorm: one block per row of 1024, 256 threads (float4 per thread)
// ---------------------------------------------------------------------------
__global__ __launch_bounds__(256) void ln_kernel(
    const float* __restrict__ x, const float* __restrict__ w,
    const float* __restrict__ b, float* __restrict__ y)
{
    int row = blockIdx.x;
    const float* xr = x + (size_t)row * kDim;
    float* yr = y + (size_t)row * kDim;
    int t = threadIdx.x;

    float4 xv = reinterpret_cast<const float4*>(xr)[t];
    float s  = xv.x + xv.y + xv.z + xv.w;
    float s2 = xv.x*xv.x + xv.y*xv.y + xv.z*xv.z + xv.w*xv.w;

    #pragma unroll
    for (int off = 16; off > 0; off >>= 1) {
        s  += __shfl_xor_sync(0xffffffffu, s,  off);
        s2 += __shfl_xor_sync(0xffffffffu, s2, off);
    }
    __shared__ float rs[8], rs2[8];
    int wid = t >> 5;
    if ((t & 31) == 0) { rs[wid] = s; rs2[wid] = s2; }
    __syncthreads();
    s = 0.f; s2 = 0.f;
    #pragma unroll
    for (int i = 0; i < 8; i++) { s += rs[i]; s2 += rs2[i]; }

    float mu  = s * (1.0f / kDim);
    float var = s2 * (1.0f / kDim) - mu * mu;
    float r   = rsqrtf(var + 1e-6f);

    float4 wv = reinterpret_cast<const float4*>(w)[t];
    float4 bv = reinterpret_cast<const float4*>(b)[t];
    float4 o;
    o.x = (xv.x - mu) * r * wv.x + bv.x;
    o.y = (xv.y - mu) * r * wv.y + bv.y;
    o.z = (xv.z - mu) * r * wv.z + bv.z;
    o.w = (xv.w - mu) * r * wv.w + bv.w;
    reinterpret_cast<float4*>(yr)[t] = o;
}

// ---------------------------------------------------------------------------
// Per-head L2 normalize: one warp per 64-dim head vector (contiguous)
// ---------------------------------------------------------------------------
__global__ __launch_bounds__(256) void l2norm_kernel(float* __restrict__ x, int nvec)
{
    int vid = blockIdx.x * 8 + (threadIdx.x >> 5);
    int l = threadIdx.x & 31;
    if (vid >= nvec) return;
    float2* p = reinterpret_cast<float2*>(x) + (size_t)vid * 32 + l;
    float2 v = *p;
    float ss = v.x * v.x + v.y * v.y;
    #pragma unroll
    for (int off = 16; off > 0; off >>= 1)
        ss += __shfl_xor_sync(0xffffffffu, ss, off);
    float inv = 1.0f / fmaxf(sqrtf(ss), 1e-6f);
    v.x *= inv; v.y *= inv;
    *p = v;
}

// ---------------------------------------------------------------------------
// Register-tiled SGEMM: C[M,N] = A[M,K] @ W[N,K]^T
// BM=BN=128, BK=8, 256 threads, 8x8 accumulators per thread.
// EPI: 0 = plain, 1 = bias + exact GELU, 2 = C = res + alpha*(acc + bias)
// M,N multiples of 128; K multiple of 8. (holds for all 6 GEMMs here)
// ---------------------------------------------------------------------------
template <int EPI>
__global__ __launch_bounds__(256) void gemm_kernel(
    const float* __restrict__ A, const float* __restrict__ W, float* __restrict__ C,
    int M, int N, int K,
    const float* __restrict__ bias, const float* __restrict__ res,
    const float* __restrict__ alpha)
{
    __shared__ float As[8][128];
    __shared__ float Ws[8][128];

    const int tid = threadIdx.x;
    const int tx = tid & 15;
    const int ty = tid >> 4;
    const int m0 = blockIdx.y * 128;
    const int n0 = blockIdx.x * 128;

    const int lr = tid >> 1;          // 0..127: tile row loaded by this thread
    const int lk = (tid & 1) * 4;     // 0 or 4: k-offset (float4)
    const float* Ag = A + (size_t)(m0 + lr) * K + lk;
    const float* Wg = W + (size_t)(n0 + lr) * K + lk;

    float acc[8][8];
    #pragma unroll
    for (int i = 0; i < 8; i++)
        #pragma unroll
        for (int j = 0; j < 8; j++) acc[i][j] = 0.f;

    for (int k0 = 0; k0 < K; k0 += 8) {
        float4 av = *reinterpret_cast<const float4*>(Ag + k0);
        float4 wv = *reinterpret_cast<const float4*>(Wg + k0);
        As[lk + 0][lr] = av.x; As[lk + 1][lr] = av.y;
        As[lk + 2][lr] = av.z; As[lk + 3][lr] = av.w;
        Ws[lk + 0][lr] = wv.x; Ws[lk + 1][lr] = wv.y;
        Ws[lk + 2][lr] = wv.z; Ws[lk + 3][lr] = wv.w;
        __syncthreads();
        #pragma unroll
        for (int kk = 0; kk < 8; kk++) {
            float a[8], bb[8];
            *reinterpret_cast<float4*>(a)      = *reinterpret_cast<const float4*>(&As[kk][ty * 8]);
            *reinterpret_cast<float4*>(a + 4)  = *reinterpret_cast<const float4*>(&As[kk][ty * 8 + 4]);
            *reinterpret_cast<float4*>(bb)     = *reinterpret_cast<const float4*>(&Ws[kk][tx * 8]);
            *reinterpret_cast<float4*>(bb + 4) = *reinterpret_cast<const float4*>(&Ws[kk][tx * 8 + 4]);
            #pragma unroll
            for (int i = 0; i < 8; i++)
                #pragma unroll
                for (int j = 0; j < 8; j++)
                    acc[i][j] = fmaf(a[i], bb[j], acc[i][j]);
        }
        __syncthreads();
    }

    float al = (EPI == 2) ? alpha[0] : 0.f;
    #pragma unroll
    for (int i = 0; i < 8; i++) {
        int row = m0 + ty * 8 + i;
        float* Cr = C + (size_t)row * N + n0 + tx * 8;
        const float* Rr = (EPI == 2) ? (res + (size_t)row * N + n0 + tx * 8) : nullptr;
        #pragma unroll
        for (int j = 0; j < 8; j++) {
            float v = acc[i][j];
            if (EPI == 1) {
                v += bias[n0 + tx * 8 + j];
                Cr[j] = 0.5f * v * (1.0f + erff(v * 0.7071067811865475f));
            } else if (EPI == 2) {
                v += bias[n0 + tx * 8 + j];
                Cr[j] = Rr[j] + al * v;
            } else {
                Cr[j] = v;
            }
        }
    }
}

// ---------------------------------------------------------------------------
// Fused attention (flash-style online softmax).
// Grid: (B*H, Lq/16). Block: 128 threads (4 warps x 4 queries each).
// Per KV tile (64 keys): S = Q K^T / TAU, online softmax, O += P V.
// ---------------------------------------------------------------------------
__global__ __launch_bounds__(128) void attn_kernel(
    const float* __restrict__ q, const float* __restrict__ k,
    const float* __restrict__ v, float* __restrict__ ctx)
{
    __shared__ float Qs[16][64];
    __shared__ float Ks[64][65];   // padded: conflict-free row access
    __shared__ float Vs[64][64];   // unpadded: float2-friendly
    __shared__ float Ps[16][64];   // per-tile probabilities (warp-private rows)

    const int bh = blockIdx.x;
    const int b = bh >> 4, h = bh & 15;
    const int q0 = blockIdx.y * 16;
    const int tid = threadIdx.x;
    const int w = tid >> 5, l = tid & 31;

    // Load Q tile [16 x 64]
    for (int i = tid; i < 16 * 16; i += 128) {
        int r = i >> 4, c4 = (i & 15) * 4;
        float4 qv = *reinterpret_cast<const float4*>(
            &q[((size_t)(b * kLq + q0 + r)) * kDim + h * kHd + c4]);
        *reinterpret_cast<float4*>(&Qs[r][c4]) = qv;
    }

    float mrun[4], lsum[4], o0[4], o1[4];
    #pragma unroll
    for (int i = 0; i < 4; i++) { mrun[i] = -1e30f; lsum[i] = 0.f; o0[i] = 0.f; o1[i] = 0.f; }

    for (int kv0 = 0; kv0 < kLkv; kv0 += 64) {
        __syncthreads();  // Ks/Vs safe to overwrite; also fences the Q loads
        for (int i = tid; i < 64 * 16; i += 128) {
            int r = i >> 4, c4 = (i & 15) * 4;
            size_t gi = ((size_t)(b * kLkv + kv0 + r)) * kDim + h * kHd + c4;
            float4 kv = *reinterpret_cast<const float4*>(&k[gi]);
            Ks[r][c4 + 0] = kv.x; Ks[r][c4 + 1] = kv.y;
            Ks[r][c4 + 2] = kv.z; Ks[r][c4 + 3] = kv.w;
            float4 vv = *reinterpret_cast<const float4*>(&v[gi]);
            *reinterpret_cast<float4*>(&Vs[r][c4]) = vv;
        }
        __syncthreads();

        #pragma unroll
        for (int qq = 0; qq < 4; qq++) {
            const int qi = w * 4 + qq;
            float s0 = 0.f, s1 = 0.f;
            #pragma unroll
            for (int kk = 0; kk < 64; kk++) {
                float qv = Qs[qi][kk];
                s0 = fmaf(qv, Ks[l][kk],      s0);
                s1 = fmaf(qv, Ks[l + 32][kk], s1);
            }
            s0 *= 0.5f;  // 1/TAU
            s1 *= 0.5f;

            float tm = fmaxf(s0, s1);
            #pragma unroll
            for (int off = 16; off > 0; off >>= 1)
                tm = fmaxf(tm, __shfl_xor_sync(0xffffffffu, tm, off));
            float nm = fmaxf(mrun[qq], tm);
            float sc = __expf(mrun[qq] - nm);
            float p0 = __expf(s0 - nm), p1 = __expf(s1 - nm);
            float ps = p0 + p1;
            #pragma unroll
            for (int off = 16; off > 0; off >>= 1)
                ps += __shfl_xor_sync(0xffffffffu, ps, off);
            lsum[qq] = lsum[qq] * sc + ps;
            mrun[qq] = nm;
            o0[qq] *= sc; o1[qq] *= sc;

            Ps[qi][l] = p0; Ps[qi][l + 32] = p1;
            __syncwarp();
            #pragma unroll
            for (int j = 0; j < 64; j++) {
                float pv = Ps[qi][j];
                float2 vv = *reinterpret_cast<const float2*>(&Vs[j][2 * l]);
                o0[qq] = fmaf(pv, vv.x, o0[qq]);
                o1[qq] = fmaf(pv, vv.y, o1[qq]);
            }
            __syncwarp();
        }
    }

    #pragma unroll
    for (int qq = 0; qq < 4; qq++) {
        float inv = 1.0f / lsum[qq];
        float2 out;
        out.x = o0[qq] * inv;
        out.y = o1[qq] * inv;
        *reinterpret_cast<float2*>(
            &ctx[((size_t)(b * kLq + q0 + w * 4 + qq)) * kDim + h * kHd + 2 * l]) = out;
    }
}

// ---------------------------------------------------------------------------
// kernel_launch
// ---------------------------------------------------------------------------
extern "C" void kernel_launch(void* const* d_in, const int* in_sizes, int n_in,
                              void* d_out, int out_size)
{
    const float* q_tokens   = (const float*)d_in[0];
    const float* kv_tokens  = (const float*)d_in[1];
    const float* q_ln_w     = (const float*)d_in[2];
    const float* q_ln_b     = (const float*)d_in[3];
    const float* kv_ln_w    = (const float*)d_in[4];
    const float* kv_ln_b    = (const float*)d_in[5];
    const float* mlp_ln_w   = (const float*)d_in[6];
    const float* mlp_ln_b   = (const float*)d_in[7];
    const float* Wq         = (const float*)d_in[8];
    const float* Wk         = (const float*)d_in[9];
    const float* Wv         = (const float*)d_in[10];
    const float* Wo         = (const float*)d_in[11];
    const float* bo         = (const float*)d_in[12];
    const float* fc1_w      = (const float*)d_in[13];
    const float* fc1_b      = (const float*)d_in[14];
    const float* fc2_w      = (const float*)d_in[15];
    const float* fc2_b      = (const float*)d_in[16];
    const float* alpha_attn = (const float*)d_in[17];
    const float* alpha_mlp  = (const float*)d_in[18];
    float* out = (float*)d_out;

    float* scratch = nullptr;
    cudaGetSymbolAddress((void**)&scratch, g_scratch);
    const size_t M = 1u << 20;
    float* qn  = scratch + 0 * M;   // [2048,1024] LN(q_tokens)
    float* kvn = scratch + 2 * M;   // [8192,1024] LN(kv_tokens)
    float* qp  = scratch + 10 * M;  // [2048,1024] Q (l2-normed in place)
    float* kp  = scratch + 12 * M;  // [8192,1024] K (l2-normed in place)
    float* vp  = scratch + 20 * M;  // [8192,1024] V
    float* ctx = scratch + 28 * M;  // [2048,1024] attention context
    float* hln = scratch + 30 * M;  // [2048,1024] LN(out)
    float* h1  = scratch + 32 * M;  // [2048,4096] fc1+gelu

    ln_kernel<<<kNQ, 256>>>(q_tokens, q_ln_w, q_ln_b, qn);
    ln_kernel<<<kNKV, 256>>>(kv_tokens, kv_ln_w, kv_ln_b, kvn);

    gemm_kernel<0><<<dim3(kDim / 128, kNQ / 128), 256>>>(
        qn, Wq, qp, kNQ, kDim, kDim, nullptr, nullptr, nullptr);
    gemm_kernel<0><<<dim3(kDim / 128, kNKV / 128), 256>>>(
        kvn, Wk, kp, kNKV, kDim, kDim, nullptr, nullptr, nullptr);
    gemm_kernel<0><<<dim3(kDim / 128, kNKV / 128), 256>>>(
        kvn, Wv, vp, kNKV, kDim, kDim, nullptr, nullptr, nullptr);

    l2norm_kernel<<<(kNQ * kH) / 8, 256>>>(qp, kNQ * kH);
    l2norm_kernel<<<(kNKV * kH) / 8, 256>>>(kp, kNKV * kH);

    attn_kernel<<<dim3(kB * kH, kLq / 16), 128>>>(qp, kp, vp, ctx);

    // out = q_tokens + alpha_attn * (ctx @ Wo^T + bo)
    gemm_kernel<2><<<dim3(kDim / 128, kNQ / 128), 256>>>(
        ctx, Wo, out, kNQ, kDim, kDim, bo, q_tokens, alpha_attn);

    ln_kernel<<<kNQ, 256>>>(out, mlp_ln_w, mlp_ln_b, hln);

    gemm_kernel<1><<<dim3(kMlp / 128, kNQ / 128), 256>>>(
        hln, fc1_w, h1, kNQ, kMlp, kDim, fc1_b, nullptr, nullptr);

    // out = out + alpha_mlp * (h1 @ fc2_w^T + fc2_b)
    gemm_kernel<2><<<dim3(kDim / 128, kNQ / 128), 256>>>(
        h1, fc2_w, out, kNQ, kDim, kMlp, fc2_b, out, alpha_mlp);
}

// round 2
// speedup vs baseline: 3.7577x; 3.7577x over previous
#include <cuda_runtime.h>
#include <cuda_bf16.h>
#include <cstdint>
#include <math.h>

namespace {
constexpr int kB   = 4;
constexpr int kLq  = 512;
constexpr int kLkv = 2048;
constexpr int kDim = 1024;
constexpr int kH   = 16;
constexpr int kHd  = 64;
constexpr int kMlp = 4096;
constexpr int kNQ  = kB * kLq;    // 2048
constexpr int kNKV = kB * kLkv;   // 8192
}

// Scratch arena: 160 MB static device allocation
__device__ __align__(256) unsigned char g_scratch[160u * 1024u * 1024u];

#define CP_ASYNC16(dst, src) \
    asm volatile("cp.async.cg.shared.global [%0], [%1], 16;" :: "r"(dst), "l"(src))
#define CP_COMMIT() asm volatile("cp.async.commit_group;")
#define LDSM4(r0,r1,r2,r3,addr) \
    asm volatile("ldmatrix.sync.aligned.m8n8.x4.shared.b16 {%0,%1,%2,%3}, [%4];" \
        : "=r"(r0),"=r"(r1),"=r"(r2),"=r"(r3) : "r"(addr))
#define MMA16816(d,a0,a1,a2,a3,b0,b1) \
    asm volatile("mma.sync.aligned.m16n8k16.row.col.f32.bf16.bf16.f32 " \
        "{%0,%1,%2,%3}, {%4,%5,%6,%7}, {%8,%9}, {%0,%1,%2,%3};" \
        : "+f"(d[0]),"+f"(d[1]),"+f"(d[2]),"+f"(d[3]) \
        : "r"(a0),"r"(a1),"r"(a2),"r"(a3),"r"(b0),"r"(b1))

// ---------------------------------------------------------------------------
// f32 -> bf16 convert (n multiple of 4)
// ---------------------------------------------------------------------------
__global__ __launch_bounds__(256) void cvt_bf16_kernel(
    const float* __restrict__ x, __nv_bfloat16* __restrict__ y, int n)
{
    int i = (blockIdx.x * 256 + threadIdx.x) * 4;
    if (i < n) {
        float4 v = *reinterpret_cast<const float4*>(x + i);
        __nv_bfloat162 lo = __floats2bfloat162_rn(v.x, v.y);
        __nv_bfloat162 hi = __floats2bfloat162_rn(v.z, v.w);
        *reinterpret_cast<__nv_bfloat162*>(y + i)     = lo;
        *reinterpret_cast<__nv_bfloat162*>(y + i + 2) = hi;
    }
}

// ---------------------------------------------------------------------------
// LayerNorm (fp32 in -> bf16 out): one block per 1024-row, 256 threads
// ---------------------------------------------------------------------------
__global__ __launch_bounds__(256) void ln_bf16_kernel(
    const float* __restrict__ x, const float* __restrict__ w,
    const float* __restrict__ b, __nv_bfloat16* __restrict__ y)
{
    int row = blockIdx.x;
    const float* xr = x + (size_t)row * kDim;
    __nv_bfloat16* yr = y + (size_t)row * kDim;
    int t = threadIdx.x;

    float4 xv = reinterpret_cast<const float4*>(xr)[t];
    float s  = xv.x + xv.y + xv.z + xv.w;
    float s2 = xv.x*xv.x + xv.y*xv.y + xv.z*xv.z + xv.w*xv.w;

    #pragma unroll
    for (int off = 16; off > 0; off >>= 1) {
        s  += __shfl_xor_sync(0xffffffffu, s,  off);
        s2 += __shfl_xor_sync(0xffffffffu, s2, off);
    }
    __shared__ float rs[8], rs2[8];
    int wid = t >> 5;
    if ((t & 31) == 0) { rs[wid] = s; rs2[wid] = s2; }
    __syncthreads();
    s = 0.f; s2 = 0.f;
    #pragma unroll
    for (int i = 0; i < 8; i++) { s += rs[i]; s2 += rs2[i]; }

    float mu  = s * (1.0f / kDim);
    float var = s2 * (1.0f / kDim) - mu * mu;
    float r   = rsqrtf(var + 1e-6f);

    float4 wv = reinterpret_cast<const float4*>(w)[t];
    float4 bv = reinterpret_cast<const float4*>(b)[t];
    float o0 = (xv.x - mu) * r * wv.x + bv.x;
    float o1 = (xv.y - mu) * r * wv.y + bv.y;
    float o2 = (xv.z - mu) * r * wv.z + bv.z;
    float o3 = (xv.w - mu) * r * wv.w + bv.w;
    reinterpret_cast<__nv_bfloat162*>(yr)[2*t]   = __floats2bfloat162_rn(o0, o1);
    reinterpret_cast<__nv_bfloat162*>(yr)[2*t+1] = __floats2bfloat162_rn(o2, o3);
}

// ---------------------------------------------------------------------------
// Per-head L2 normalize in-place (fp32), one warp per 64-dim vector
// ---------------------------------------------------------------------------
__global__ __launch_bounds__(256) void l2norm_kernel(float* __restrict__ x, int nvec)
{
    int vid = blockIdx.x * 8 + (threadIdx.x >> 5);
    int l = threadIdx.x & 31;
    if (vid >= nvec) return;
    float2* p = reinterpret_cast<float2*>(x) + (size_t)vid * 32 + l;
    float2 v = *p;
    float ss = v.x * v.x + v.y * v.y;
    #pragma unroll
    for (int off = 16; off > 0; off >>= 1)
        ss += __shfl_xor_sync(0xffffffffu, ss, off);
    float inv = 1.0f / fmaxf(sqrtf(ss), 1e-6f);
    v.x *= inv; v.y *= inv;
    *p = v;
}

// ---------------------------------------------------------------------------
// bf16 tensor-core GEMM: C[M,N] = A[M,K] @ W[N,K]^T  (fp32 accumulate)
// BM=BN=128, BK=64, 256 threads (8 warps, 4x2, warp tile 32x64), 2-stage cp.async.
// EPI 0: Cf fp32.  EPI 1: bf16 GELU(acc+bias) -> Cb.  EPI 2: Cf = res + alpha*(acc+bias).
// ---------------------------------------------------------------------------
template <int EPI>
__global__ __launch_bounds__(256) void gemm_bf16_kernel(
    const __nv_bfloat16* __restrict__ A, const __nv_bfloat16* __restrict__ W,
    int M, int N, int K,
    const float* __restrict__ bias, const float* __restrict__ res,
    const float* __restrict__ alpha,
    float* __restrict__ Cf, __nv_bfloat16* __restrict__ Cb)
{
    extern __shared__ char smem_raw[];
    const uint32_t smem = (uint32_t)__cvta_generic_to_shared(smem_raw);

    const int tid  = threadIdx.x;
    const int lane = tid & 31;
    const int w    = tid >> 5;
    const int wm   = (w & 3) << 5;   // warp m offset in tile
    const int wn   = (w >> 2) << 6;  // warp n offset in tile
    const long m0  = (long)blockIdx.y << 7;
    const long n0  = (long)blockIdx.x << 7;

    const int lrow   = tid >> 3;     // 0..31
    const int lchunk = tid & 7;      // 0..7 (16B chunks within 128B row)
    const uint32_t lsw = ((uint32_t)(lchunk ^ (lrow & 7))) << 4;
    const __nv_bfloat16* Ag = A + (m0 + lrow) * K + lchunk * 8;
    const __nv_bfloat16* Wg = W + (n0 + lrow) * K + lchunk * 8;

    float acc[2][8][4];
    #pragma unroll
    for (int i = 0; i < 2; i++)
        #pragma unroll
        for (int j = 0; j < 8; j++)
            #pragma unroll
            for (int c = 0; c < 4; c++) acc[i][j][c] = 0.f;

    const int T = K >> 6;

    // prologue: load tile 0 into stage 0
    {
        uint32_t sA = smem, sB = smem + 16384;
        #pragma unroll
        for (int p = 0; p < 4; p++) {
            uint32_t doff = (lrow + p * 32) * 128 + lsw;
            CP_ASYNC16(sA + doff, Ag + (long)p * 32 * K);
            CP_ASYNC16(sB + doff, Wg + (long)p * 32 * K);
        }
        CP_COMMIT();
    }

    for (int kt = 0; kt < T; kt++) {
        int s = kt & 1;
        if (kt + 1 < T) {
            uint32_t sA = smem + (s ^ 1) * 32768, sB = sA + 16384;
            const __nv_bfloat16* a = Ag + (long)(kt + 1) * 64;
            const __nv_bfloat16* b = Wg + (long)(kt + 1) * 64;
            #pragma unroll
            for (int p = 0; p < 4; p++) {
                uint32_t doff = (lrow + p * 32) * 128 + lsw;
                CP_ASYNC16(sA + doff, a + (long)p * 32 * K);
                CP_ASYNC16(sB + doff, b + (long)p * 32 * K);
            }
            CP_COMMIT();
            asm volatile("cp.async.wait_group 1;");
        } else {
            asm volatile("cp.async.wait_group 0;");
        }
        __syncthreads();

        uint32_t sA = smem + s * 32768, sB = sA + 16384;
        #pragma unroll
        for (int ks = 0; ks < 4; ks++) {
            uint32_t afr[2][4];
            #pragma unroll
            for (int im = 0; im < 2; im++) {
                int row = wm + im * 16 + (lane & 15);
                int ch  = ks * 2 + (lane >> 4);
                uint32_t addr = sA + row * 128 + ((uint32_t)(ch ^ (row & 7)) << 4);
                LDSM4(afr[im][0], afr[im][1], afr[im][2], afr[im][3], addr);
            }
            uint32_t bfr[8][2];
            #pragma unroll
            for (int ib = 0; ib < 4; ib++) {
                int row = wn + ib * 16 + ((lane >> 4) << 3) + (lane & 7);
                int ch  = ks * 2 + ((lane >> 3) & 1);
                uint32_t addr = sB + row * 128 + ((uint32_t)(ch ^ (row & 7)) << 4);
                uint32_t r0, r1, r2, r3;
                LDSM4(r0, r1, r2, r3, addr);
                bfr[2*ib][0] = r0; bfr[2*ib][1] = r1;
                bfr[2*ib+1][0] = r2; bfr[2*ib+1][1] = r3;
            }
            #pragma unroll
            for (int im = 0; im < 2; im++)
                #pragma unroll
                for (int in = 0; in < 8; in++)
                    MMA16816(acc[im][in], afr[im][0], afr[im][1], afr[im][2], afr[im][3],
                             bfr[in][0], bfr[in][1]);
        }
        __syncthreads();
    }

    // epilogue
    const int g = lane >> 2, tg = lane & 3;
    float al = (EPI == 2) ? alpha[0] : 0.f;
    #pragma unroll
    for (int im = 0; im < 2; im++) {
        long r0 = m0 + wm + im * 16 + g;
        #pragma unroll
        for (int in = 0; in < 8; in++) {
            long c = n0 + wn + in * 8 + tg * 2;
            float v0 = acc[im][in][0], v1 = acc[im][in][1];
            float v2 = acc[im][in][2], v3 = acc[im][in][3];
            if (EPI == 0) {
                *reinterpret_cast<float2*>(&Cf[r0 * N + c])       = make_float2(v0, v1);
                *reinterpret_cast<float2*>(&Cf[(r0 + 8) * N + c]) = make_float2(v2, v3);
            } else if (EPI == 1) {
                float b0 = bias[c], b1 = bias[c + 1];
                v0 += b0; v1 += b1; v2 += b0; v3 += b1;
                const float is2 = 0.7071067811865475f;
                v0 = 0.5f * v0 * (1.f + erff(v0 * is2));
                v1 = 0.5f * v1 * (1.f + erff(v1 * is2));
                v2 = 0.5f * v2 * (1.f + erff(v2 * is2));
                v3 = 0.5f * v3 * (1.f + erff(v3 * is2));
                *reinterpret_cast<__nv_bfloat162*>(&Cb[r0 * N + c]) =
                    __floats2bfloat162_rn(v0, v1);
                *reinterpret_cast<__nv_bfloat162*>(&Cb[(r0 + 8) * N + c]) =
                    __floats2bfloat162_rn(v2, v3);
            } else {
                float b0 = bias[c], b1 = bias[c + 1];
                float2 ra = *reinterpret_cast<const float2*>(&res[r0 * N + c]);
                float2 rb = *reinterpret_cast<const float2*>(&res[(r0 + 8) * N + c]);
                *reinterpret_cast<float2*>(&Cf[r0 * N + c]) =
                    make_float2(ra.x + al * (v0 + b0), ra.y + al * (v1 + b1));
                *reinterpret_cast<float2*>(&Cf[(r0 + 8) * N + c]) =
                    make_float2(rb.x + al * (v2 + b0), rb.y + al * (v3 + b1));
            }
        }
    }
}

// ---------------------------------------------------------------------------
// Register-tiled flash attention (fp32 math, bf16 ctx output).
// Grid: (B*H, Lq/32). Block 128 threads: thread(ty 0..7, tx 0..15) owns
// 4 queries x 4 keys (scores) and 4 queries x 4 dims (output).
// ---------------------------------------------------------------------------
__global__ __launch_bounds__(128) void attn_kernel(
    const float* __restrict__ q, const float* __restrict__ k,
    const float* __restrict__ v, __nv_bfloat16* __restrict__ ctx)
{
    __shared__ float Qt[64][36];   // Q transposed: [dim][query]
    __shared__ float KV[64][68];   // K transposed [dim][key], then V [key][dim]
    __shared__ float Ps[32][68];   // probabilities [query][key]

    const int bh = blockIdx.x;
    const int b = bh >> 4, h = bh & 15;
    const int q0 = blockIdx.y * 32;
    const int tid = threadIdx.x;
    const int tx = tid & 15, ty = tid >> 4;

    // Load Q tile transposed: 32 q x 64 dims
    #pragma unroll
    for (int it = 0; it < 4; it++) {
        int idx = tid + it * 128;           // 0..511
        int qi = idx >> 4;                  // 0..31
        int dc = (idx & 15) * 4;            // 0..60
        float4 qv = *reinterpret_cast<const float4*>(
            &q[((size_t)(b * kLq + q0 + qi)) * kDim + h * kHd + dc]);
        Qt[dc + 0][qi] = qv.x; Qt[dc + 1][qi] = qv.y;
        Qt[dc + 2][qi] = qv.z; Qt[dc + 3][qi] = qv.w;
    }

    float O[4][4];
    float mrun[4], lsum[4];
    #pragma unroll
    for (int i = 0; i < 4; i++) {
        mrun[i] = -1e30f; lsum[i] = 0.f;
        #pragma unroll
        for (int c = 0; c < 4; c++) O[i][c] = 0.f;
    }

    for (int kv0 = 0; kv0 < kLkv; kv0 += 64) {
        __syncthreads();  // prior tile's PV reads of KV/Ps done; Q visible on first iter
        // K transposed load: KV[dim][key]
        #pragma unroll
        for (int it = 0; it < 8; it++) {
            int idx = tid + it * 128;       // 0..1023
            int key = idx & 63;
            int dc = (idx >> 6) * 4;
            float4 kv4 = *reinterpret_cast<const float4*>(
                &k[((size_t)(b * kLkv + kv0 + key)) * kDim + h * kHd + dc]);
            KV[dc + 0][key] = kv4.x; KV[dc + 1][key] = kv4.y;
            KV[dc + 2][key] = kv4.z; KV[dc + 3][key] = kv4.w;
        }
        __syncthreads();

        // scores S[4q][4k]
        float S[4][4];
        #pragma unroll
        for (int i = 0; i < 4; i++)
            #pragma unroll
            for (int j = 0; j < 4; j++) S[i][j] = 0.f;

        #pragma unroll 4
        for (int kk = 0; kk < 64; kk++) {
            float4 qv = *reinterpret_cast<const float4*>(&Qt[kk][ty * 4]);
            float4 kv4 = *reinterpret_cast<const float4*>(&KV[kk][tx * 4]);
            float qa[4] = {qv.x, qv.y, qv.z, qv.w};
            float ka[4] = {kv4.x, kv4.y, kv4.z, kv4.w};
            #pragma unroll
            for (int i = 0; i < 4; i++)
                #pragma unroll
                for (int j = 0; j < 4; j++)
                    S[i][j] = fmaf(qa[i], ka[j], S[i][j]);
        }

        // online softmax (per q row; 16 tx lanes share a row)
        float P[4][4];
        #pragma unroll
        for (int i = 0; i < 4; i++) {
            float tm = fmaxf(fmaxf(S[i][0], S[i][1]), fmaxf(S[i][2], S[i][3])) * 0.5f;
            #pragma unroll
            for (int off = 8; off > 0; off >>= 1)
                tm = fmaxf(tm, __shfl_xor_sync(0xffffffffu, tm, off));
            float nm = fmaxf(mrun[i], tm);
            float sc = __expf(mrun[i] - nm);
            float rs = 0.f;
            #pragma unroll
            for (int j = 0; j < 4; j++) {
                P[i][j] = __expf(S[i][j] * 0.5f - nm);
                rs += P[i][j];
            }
            #pragma unroll
            for (int off = 8; off > 0; off >>= 1)
                rs += __shfl_xor_sync(0xffffffffu, rs, off);
            lsum[i] = lsum[i] * sc + rs;
            mrun[i] = nm;
            #pragma unroll
            for (int c = 0; c < 4; c++) O[i][c] *= sc;
        }
        #pragma unroll
        for (int i = 0; i < 4; i++)
            *reinterpret_cast<float4*>(&Ps[ty * 4 + i][tx * 4]) =
                make_float4(P[i][0], P[i][1], P[i][2], P[i][3]);
        __syncthreads();

        // V load (row-major, overwrites KV)
        #pragma unroll
        for (int it = 0; it < 8; it++) {
            int idx = tid + it * 128;
            int key = idx >> 4;             // 0..63
            int dc = (idx & 15) * 4;
            float4 vv = *reinterpret_cast<const float4*>(
                &v[((size_t)(b * kLkv + kv0 + key)) * kDim + h * kHd + dc]);
            *reinterpret_cast<float4*>(&KV[key][dc]) = vv;
        }
        __syncthreads();

        // O[4q][4d] += P[q][j] * V[j][d]
        #pragma unroll 4
        for (int j = 0; j < 64; j++) {
            float4 vv = *reinterpret_cast<const float4*>(&KV[j][tx * 4]);
            float va[4] = {vv.x, vv.y, vv.z, vv.w};
            float pj[4];
            #pragma unroll
            for (int i = 0; i < 4; i++) pj[i] = Ps[ty * 4 + i][j];
            #pragma unroll
            for (int i = 0; i < 4; i++)
                #pragma unroll
                for (int c = 0; c < 4; c++)
                    O[i][c] = fmaf(pj[i], va[c], O[i][c]);
        }
    }

    // write ctx (bf16)
    #pragma unroll
    for (int i = 0; i < 4; i++) {
        float inv = 1.0f / lsum[i];
        size_t base = ((size_t)(b * kLq + q0 + ty * 4 + i)) * kDim + h * kHd + tx * 4;
        *reinterpret_cast<__nv_bfloat162*>(&ctx[base]) =
            __floats2bfloat162_rn(O[i][0] * inv, O[i][1] * inv);
        *reinterpret_cast<__nv_bfloat162*>(&ctx[base + 2]) =
            __floats2bfloat162_rn(O[i][2] * inv, O[i][3] * inv);
    }
}

// ---------------------------------------------------------------------------
// kernel_launch
// ---------------------------------------------------------------------------
extern "C" void kernel_launch(void* const* d_in, const int* in_sizes, int n_in,
                              void* d_out, int out_size)
{
    const float* q_tokens   = (const float*)d_in[0];
    const float* kv_tokens  = (const float*)d_in[1];
    const float* q_ln_w     = (const float*)d_in[2];
    const float* q_ln_b     = (const float*)d_in[3];
    const float* kv_ln_w    = (const float*)d_in[4];
    const float* kv_ln_b    = (const float*)d_in[5];
    const float* mlp_ln_w   = (const float*)d_in[6];
    const float* mlp_ln_b   = (const float*)d_in[7];
    const float* Wq         = (const float*)d_in[8];
    const float* Wk         = (const float*)d_in[9];
    const float* Wv         = (const float*)d_in[10];
    const float* Wo         = (const float*)d_in[11];
    const float* bo         = (const float*)d_in[12];
    const float* fc1_w      = (const float*)d_in[13];
    const float* fc1_b      = (const float*)d_in[14];
    const float* fc2_w      = (const float*)d_in[15];
    const float* fc2_b      = (const float*)d_in[16];
    const float* alpha_attn = (const float*)d_in[17];
    const float* alpha_mlp  = (const float*)d_in[18];
    float* out = (float*)d_out;

    unsigned char* arena = nullptr;
    cudaGetSymbolAddress((void**)&arena, g_scratch);
    const size_t MB = 1024u * 1024u;

    __nv_bfloat16* qn   = (__nv_bfloat16*)(arena + 0 * MB);    // 4 MB
    __nv_bfloat16* kvn  = (__nv_bfloat16*)(arena + 4 * MB);    // 16 MB
    __nv_bfloat16* Wqb  = (__nv_bfloat16*)(arena + 20 * MB);   // 2 MB
    __nv_bfloat16* Wkb  = (__nv_bfloat16*)(arena + 22 * MB);   // 2 MB
    __nv_bfloat16* Wvb  = (__nv_bfloat16*)(arena + 24 * MB);   // 2 MB
    __nv_bfloat16* Wob  = (__nv_bfloat16*)(arena + 26 * MB);   // 2 MB
    __nv_bfloat16* fc1b = (__nv_bfloat16*)(arena + 28 * MB);   // 8 MB
    __nv_bfloat16* fc2b = (__nv_bfloat16*)(arena + 36 * MB);   // 8 MB
    float*         qf   = (float*)(arena + 44 * MB);           // 8 MB
    float*         kf   = (float*)(arena + 52 * MB);           // 32 MB
    float*         vf   = (float*)(arena + 84 * MB);           // 32 MB
    __nv_bfloat16* ctxb = (__nv_bfloat16*)(arena + 116 * MB);  // 4 MB
    __nv_bfloat16* hln  = (__nv_bfloat16*)(arena + 120 * MB);  // 4 MB
    __nv_bfloat16* h1b  = (__nv_bfloat16*)(arena + 124 * MB);  // 16 MB

    // opt-in to 64KB dynamic smem for the GEMMs (idempotent)
    cudaFuncSetAttribute(gemm_bf16_kernel<0>, cudaFuncAttributeMaxDynamicSharedMemorySize, 65536);
    cudaFuncSetAttribute(gemm_bf16_kernel<1>, cudaFuncAttributeMaxDynamicSharedMemorySize, 65536);
    cudaFuncSetAttribute(gemm_bf16_kernel<2>, cudaFuncAttributeMaxDynamicSharedMemorySize, 65536);

    // weight converts
    cvt_bf16_kernel<<<(kDim * kDim) / 1024, 256>>>(Wq, Wqb, kDim * kDim);
    cvt_bf16_kernel<<<(kDim * kDim) / 1024, 256>>>(Wk, Wkb, kDim * kDim);
    cvt_bf16_kernel<<<(kDim * kDim) / 1024, 256>>>(Wv, Wvb, kDim * kDim);
    cvt_bf16_kernel<<<(kDim * kDim) / 1024, 256>>>(Wo, Wob, kDim * kDim);
    cvt_bf16_kernel<<<(kMlp * kDim) / 1024, 256>>>(fc1_w, fc1b, kMlp * kDim);
    cvt_bf16_kernel<<<(kMlp * kDim) / 1024, 256>>>(fc2_w, fc2b, kMlp * kDim);

    ln_bf16_kernel<<<kNQ, 256>>>(q_tokens, q_ln_w, q_ln_b, qn);
    ln_bf16_kernel<<<kNKV, 256>>>(kv_tokens, kv_ln_w, kv_ln_b, kvn);

    // Q/K/V projections (fp32 out)
    gemm_bf16_kernel<0><<<dim3(kDim / 128, kNQ / 128), 256, 65536>>>(
        qn, Wqb, kNQ, kDim, kDim, nullptr, nullptr, nullptr, qf, nullptr);
    gemm_bf16_kernel<0><<<dim3(kDim / 128, kNKV / 128), 256, 65536>>>(
        kvn, Wkb, kNKV, kDim, kDim, nullptr, nullptr, nullptr, kf, nullptr);
    gemm_bf16_kernel<0><<<dim3(kDim / 128, kNKV / 128), 256, 65536>>>(
        kvn, Wvb, kNKV, kDim, kDim, nullptr, nullptr, nullptr, vf, nullptr);

    l2norm_kernel<<<(kNQ * kH) / 8, 256>>>(qf, kNQ * kH);
    l2norm_kernel<<<(kNKV * kH) / 8, 256>>>(kf, kNKV * kH);

    attn_kernel<<<dim3(kB * kH, kLq / 32), 128>>>(qf, kf, vf, ctxb);

    // out = q_tokens + alpha_attn * (ctx @ Wo^T + bo)
    gemm_bf16_kernel<2><<<dim3(kDim / 128, kNQ / 128), 256, 65536>>>(
        ctxb, Wob, kNQ, kDim, kDim, bo, q_tokens, alpha_attn, out, nullptr);

    ln_bf16_kernel<<<kNQ, 256>>>(out, mlp_ln_w, mlp_ln_b, hln);

    // h1 = gelu(hln @ fc1^T + b1) (bf16 out)
    gemm_bf16_kernel<1><<<dim3(kMlp / 128, kNQ / 128), 256, 65536>>>(
        hln, fc1b, kNQ, kMlp, kDim, fc1_b, nullptr, nullptr, nullptr, h1b);

    // out = out + alpha_mlp * (h1 @ fc2^T + b2)
    gemm_bf16_kernel<2><<<dim3(kDim / 128, kNQ / 128), 256, 65536>>>(
        h1b, fc2b, kNQ, kDim, kMlp, fc2_b, out, alpha_mlp, out, nullptr);
}

// round 3
// speedup vs baseline: 10.1152x; 2.6918x over previous
#include <cuda_runtime.h>
#include <cuda_bf16.h>
#include <cstdint>
#include <math.h>

namespace {
constexpr int kB   = 4;
constexpr int kLq  = 512;
constexpr int kLkv = 2048;
constexpr int kDim = 1024;
constexpr int kH   = 16;
constexpr int kMlp = 4096;
constexpr int kNQ  = kB * kLq;    // 2048
constexpr int kNKV = kB * kLkv;   // 8192
}

__device__ __align__(256) unsigned char g_scratch[160u * 1024u * 1024u];

#define CP_ASYNC16(dst, src) \
    asm volatile("cp.async.cg.shared.global [%0], [%1], 16;" :: "r"(dst), "l"(src))
#define CP_COMMIT() asm volatile("cp.async.commit_group;")
#define LDSM4(r0,r1,r2,r3,addr) \
    asm volatile("ldmatrix.sync.aligned.m8n8.x4.shared.b16 {%0,%1,%2,%3}, [%4];" \
        : "=r"(r0),"=r"(r1),"=r"(r2),"=r"(r3) : "r"(addr))
#define LDSM4T(r0,r1,r2,r3,addr) \
    asm volatile("ldmatrix.sync.aligned.m8n8.x4.trans.shared.b16 {%0,%1,%2,%3}, [%4];" \
        : "=r"(r0),"=r"(r1),"=r"(r2),"=r"(r3) : "r"(addr))
#define MMA16816(d,a0,a1,a2,a3,b0,b1) \
    asm volatile("mma.sync.aligned.m16n8k16.row.col.f32.bf16.bf16.f32 " \
        "{%0,%1,%2,%3}, {%4,%5,%6,%7}, {%8,%9}, {%0,%1,%2,%3};" \
        : "+f"(d[0]),"+f"(d[1]),"+f"(d[2]),"+f"(d[3]) \
        : "r"(a0),"r"(a1),"r"(a2),"r"(a3),"r"(b0),"r"(b1))

__device__ __forceinline__ uint32_t pack_bf16(float a, float b) {
    __nv_bfloat162 t = __floats2bfloat162_rn(a, b);
    return *reinterpret_cast<uint32_t*>(&t);
}

// ---------------------------------------------------------------------------
// f32 -> bf16 convert
// ---------------------------------------------------------------------------
__global__ __launch_bounds__(256) void cvt_bf16_kernel(
    const float* __restrict__ x, __nv_bfloat16* __restrict__ y, int n)
{
    int i = (blockIdx.x * 256 + threadIdx.x) * 4;
    if (i < n) {
        float4 v = *reinterpret_cast<const float4*>(x + i);
        *reinterpret_cast<__nv_bfloat162*>(y + i)     = __floats2bfloat162_rn(v.x, v.y);
        *reinterpret_cast<__nv_bfloat162*>(y + i + 2) = __floats2bfloat162_rn(v.z, v.w);
    }
}

// ---------------------------------------------------------------------------
// LayerNorm (fp32 -> bf16)
// ---------------------------------------------------------------------------
__global__ __launch_bounds__(256) void ln_bf16_kernel(
    const float* __restrict__ x, const float* __restrict__ w,
    const float* __restrict__ b, __nv_bfloat16* __restrict__ y)
{
    int row = blockIdx.x;
    const float* xr = x + (size_t)row * kDim;
    __nv_bfloat16* yr = y + (size_t)row * kDim;
    int t = threadIdx.x;

    float4 xv = reinterpret_cast<const float4*>(xr)[t];
    float s  = xv.x + xv.y + xv.z + xv.w;
    float s2 = xv.x*xv.x + xv.y*xv.y + xv.z*xv.z + xv.w*xv.w;

    #pragma unroll
    for (int off = 16; off > 0; off >>= 1) {
        s  += __shfl_xor_sync(0xffffffffu, s,  off);
        s2 += __shfl_xor_sync(0xffffffffu, s2, off);
    }
    __shared__ float rs[8], rs2[8];
    int wid = t >> 5;
    if ((t & 31) == 0) { rs[wid] = s; rs2[wid] = s2; }
    __syncthreads();
    s = 0.f; s2 = 0.f;
    #pragma unroll
    for (int i = 0; i < 8; i++) { s += rs[i]; s2 += rs2[i]; }

    float mu  = s * (1.0f / kDim);
    float var = s2 * (1.0f / kDim) - mu * mu;
    float r   = rsqrtf(var + 1e-6f);

    float4 wv = reinterpret_cast<const float4*>(w)[t];
    float4 bv = reinterpret_cast<const float4*>(b)[t];
    reinterpret_cast<__nv_bfloat162*>(yr)[2*t] =
        __floats2bfloat162_rn((xv.x - mu) * r * wv.x + bv.x,
                              (xv.y - mu) * r * wv.y + bv.y);
    reinterpret_cast<__nv_bfloat162*>(yr)[2*t+1] =
        __floats2bfloat162_rn((xv.z - mu) * r * wv.z + bv.z,
                              (xv.w - mu) * r * wv.w + bv.w);
}

// ---------------------------------------------------------------------------
// bf16 tensor-core GEMM: C[M,N] = A[M,K] @ W[N,K]^T (fp32 accum)
// EPI 1: bf16 GELU(acc+bias).  EPI 2: fp32 res + alpha*(acc+bias).
// EPI 3: bf16 per-head L2-norm (head = 64 cols = warp n-tile).  EPI 4: bf16 plain.
// ---------------------------------------------------------------------------
template <int EPI>
__global__ __launch_bounds__(256) void gemm_bf16_kernel(
    const __nv_bfloat16* __restrict__ A, const __nv_bfloat16* __restrict__ W,
    int M, int N, int K,
    const float* __restrict__ bias, const float* __restrict__ res,
    const float* __restrict__ alpha,
    float* __restrict__ Cf, __nv_bfloat16* __restrict__ Cb)
{
    extern __shared__ char smem_raw[];
    const uint32_t smem = (uint32_t)__cvta_generic_to_shared(smem_raw);

    const int tid  = threadIdx.x;
    const int lane = tid & 31;
    const int w    = tid >> 5;
    const int wm   = (w & 3) << 5;
    const int wn   = (w >> 2) << 6;
    const long m0  = (long)blockIdx.y << 7;
    const long n0  = (long)blockIdx.x << 7;

    const int lrow   = tid >> 3;
    const int lchunk = tid & 7;
    const uint32_t lsw = ((uint32_t)(lchunk ^ (lrow & 7))) << 4;
    const __nv_bfloat16* Ag = A + (m0 + lrow) * K + lchunk * 8;
    const __nv_bfloat16* Wg = W + (n0 + lrow) * K + lchunk * 8;

    float acc[2][8][4];
    #pragma unroll
    for (int i = 0; i < 2; i++)
        #pragma unroll
        for (int j = 0; j < 8; j++)
            #pragma unroll
            for (int c = 0; c < 4; c++) acc[i][j][c] = 0.f;

    const int T = K >> 6;

    {
        uint32_t sA = smem, sB = smem + 16384;
        #pragma unroll
        for (int p = 0; p < 4; p++) {
            uint32_t doff = (lrow + p * 32) * 128 + lsw;
            CP_ASYNC16(sA + doff, Ag + (long)p * 32 * K);
            CP_ASYNC16(sB + doff, Wg + (long)p * 32 * K);
        }
        CP_COMMIT();
    }

    for (int kt = 0; kt < T; kt++) {
        int s = kt & 1;
        if (kt + 1 < T) {
            uint32_t sA = smem + (s ^ 1) * 32768, sB = sA + 16384;
            const __nv_bfloat16* a = Ag + (long)(kt + 1) * 64;
            const __nv_bfloat16* b = Wg + (long)(kt + 1) * 64;
            #pragma unroll
            for (int p = 0; p < 4; p++) {
                uint32_t doff = (lrow + p * 32) * 128 + lsw;
                CP_ASYNC16(sA + doff, a + (long)p * 32 * K);
                CP_ASYNC16(sB + doff, b + (long)p * 32 * K);
            }
            CP_COMMIT();
            asm volatile("cp.async.wait_group 1;");
        } else {
            asm volatile("cp.async.wait_group 0;");
        }
        __syncthreads();

        uint32_t sA = smem + s * 32768, sB = sA + 16384;
        #pragma unroll
        for (int ks = 0; ks < 4; ks++) {
            uint32_t afr[2][4];
            #pragma unroll
            for (int im = 0; im < 2; im++) {
                int row = wm + im * 16 + (lane & 15);
                int ch  = ks * 2 + (lane >> 4);
                uint32_t addr = sA + row * 128 + ((uint32_t)(ch ^ (row & 7)) << 4);
                LDSM4(afr[im][0], afr[im][1], afr[im][2], afr[im][3], addr);
            }
            uint32_t bfr[8][2];
            #pragma unroll
            for (int ib = 0; ib < 4; ib++) {
                int row = wn + ib * 16 + ((lane >> 4) << 3) + (lane & 7);
                int ch  = ks * 2 + ((lane >> 3) & 1);
                uint32_t addr = sB + row * 128 + ((uint32_t)(ch ^ (row & 7)) << 4);
                uint32_t r0, r1, r2, r3;
                LDSM4(r0, r1, r2, r3, addr);
                bfr[2*ib][0] = r0; bfr[2*ib][1] = r1;
                bfr[2*ib+1][0] = r2; bfr[2*ib+1][1] = r3;
            }
            #pragma unroll
            for (int im = 0; im < 2; im++)
                #pragma unroll
                for (int in = 0; in < 8; in++)
                    MMA16816(acc[im][in], afr[im][0], afr[im][1], afr[im][2], afr[im][3],
                             bfr[in][0], bfr[in][1]);
        }
        __syncthreads();
    }

    const int g = lane >> 2, tg = lane & 3;
    float al = (EPI == 2) ? alpha[0] : 0.f;
    #pragma unroll
    for (int im = 0; im < 2; im++) {
        long r0 = m0 + wm + im * 16 + g;
        float inv0 = 1.f, inv1 = 1.f;
        if (EPI == 3) {
            float ss0 = 0.f, ss1 = 0.f;
            #pragma unroll
            for (int in = 0; in < 8; in++) {
                ss0 += acc[im][in][0]*acc[im][in][0] + acc[im][in][1]*acc[im][in][1];
                ss1 += acc[im][in][2]*acc[im][in][2] + acc[im][in][3]*acc[im][in][3];
            }
            ss0 += __shfl_xor_sync(0xffffffffu, ss0, 1);
            ss0 += __shfl_xor_sync(0xffffffffu, ss0, 2);
            ss1 += __shfl_xor_sync(0xffffffffu, ss1, 1);
            ss1 += __shfl_xor_sync(0xffffffffu, ss1, 2);
            inv0 = 1.0f / fmaxf(sqrtf(ss0), 1e-6f);
            inv1 = 1.0f / fmaxf(sqrtf(ss1), 1e-6f);
        }
        #pragma unroll
        for (int in = 0; in < 8; in++) {
            long c = n0 + wn + in * 8 + tg * 2;
            float v0 = acc[im][in][0], v1 = acc[im][in][1];
            float v2 = acc[im][in][2], v3 = acc[im][in][3];
            if (EPI == 1) {
                float b0 = bias[c], b1 = bias[c + 1];
                v0 += b0; v1 += b1; v2 += b0; v3 += b1;
                const float is2 = 0.7071067811865475f;
                v0 = 0.5f * v0 * (1.f + erff(v0 * is2));
                v1 = 0.5f * v1 * (1.f + erff(v1 * is2));
                v2 = 0.5f * v2 * (1.f + erff(v2 * is2));
                v3 = 0.5f * v3 * (1.f + erff(v3 * is2));
                *reinterpret_cast<__nv_bfloat162*>(&Cb[r0 * N + c]) =
                    __floats2bfloat162_rn(v0, v1);
                *reinterpret_cast<__nv_bfloat162*>(&Cb[(r0 + 8) * N + c]) =
                    __floats2bfloat162_rn(v2, v3);
            } else if (EPI == 2) {
                float b0 = bias[c], b1 = bias[c + 1];
                float2 ra = *reinterpret_cast<const float2*>(&res[r0 * N + c]);
                float2 rb = *reinterpret_cast<const float2*>(&res[(r0 + 8) * N + c]);
                *reinterpret_cast<float2*>(&Cf[r0 * N + c]) =
                    make_float2(ra.x + al * (v0 + b0), ra.y + al * (v1 + b1));
                *reinterpret_cast<float2*>(&Cf[(r0 + 8) * N + c]) =
                    make_float2(rb.x + al * (v2 + b0), rb.y + al * (v3 + b1));
            } else if (EPI == 3) {
                *reinterpret_cast<__nv_bfloat162*>(&Cb[r0 * N + c]) =
                    __floats2bfloat162_rn(v0 * inv0, v1 * inv0);
                *reinterpret_cast<__nv_bfloat162*>(&Cb[(r0 + 8) * N + c]) =
                    __floats2bfloat162_rn(v2 * inv1, v3 * inv1);
            } else {  // EPI 4
                *reinterpret_cast<__nv_bfloat162*>(&Cb[r0 * N + c]) =
                    __floats2bfloat162_rn(v0, v1);
                *reinterpret_cast<__nv_bfloat162*>(&Cb[(r0 + 8) * N + c]) =
                    __floats2bfloat162_rn(v2, v3);
            }
        }
    }
}

// ---------------------------------------------------------------------------
// Tensor-core flash attention. Grid (B*H, Lq/64), 128 threads (4 warps x 16 q).
// Q/K/V bf16 (q,k pre-l2-normalized). KV tiles of 64, double-buffered cp.async.
// ---------------------------------------------------------------------------
__global__ __launch_bounds__(128) void attn_mma_kernel(
    const __nv_bfloat16* __restrict__ q, const __nv_bfloat16* __restrict__ k,
    const __nv_bfloat16* __restrict__ v, __nv_bfloat16* __restrict__ ctx)
{
    __shared__ __align__(1024) unsigned char sm[40 * 1024];
    const uint32_t smem = (uint32_t)__cvta_generic_to_shared(sm);
    const uint32_t sQ = smem;
    // stages: K0@8K V0@16K K1@24K V1@32K

    const int bh = blockIdx.x;
    const int b = bh >> 4, h = bh & 15;
    const int q0 = blockIdx.y * 64;
    const int tid = threadIdx.x;
    const int lane = tid & 31;
    const int w = tid >> 5;

    const __nv_bfloat16* qg = q + ((size_t)(b * kLq + q0)) * kDim + h * 64;
    const __nv_bfloat16* kg = k + ((size_t)b * kLkv) * kDim + h * 64;
    const __nv_bfloat16* vg = v + ((size_t)b * kLkv) * kDim + h * 64;

    // prologue: load Q + K0 + V0
    #pragma unroll
    for (int p = 0; p < 4; p++) {
        int idx = tid + p * 128;
        int row = idx >> 3, ch = idx & 7;
        uint32_t doff = row * 128 + ((uint32_t)(ch ^ (row & 7)) << 4);
        CP_ASYNC16(sQ + doff, qg + (size_t)row * kDim + ch * 8);
        CP_ASYNC16(sQ + 8192 + doff, kg + (size_t)row * kDim + ch * 8);
        CP_ASYNC16(sQ + 16384 + doff, vg + (size_t)row * kDim + ch * 8);
    }
    CP_COMMIT();

    uint32_t qa[4][4];
    float oacc[8][4];
    #pragma unroll
    for (int j = 0; j < 8; j++)
        #pragma unroll
        for (int c = 0; c < 4; c++) oacc[j][c] = 0.f;
    float mrow[2] = {-1e30f, -1e30f};
    float lrow[2] = {0.f, 0.f};

    const int T = kLkv / 64;
    for (int t = 0; t < T; t++) {
        int s = t & 1;
        if (t + 1 < T) {
            uint32_t sK = sQ + 8192 + (s ^ 1) * 16384;
            uint32_t sV = sK + 8192;
            const __nv_bfloat16* kp = kg + (size_t)(t + 1) * 64 * kDim;
            const __nv_bfloat16* vp = vg + (size_t)(t + 1) * 64 * kDim;
            #pragma unroll
            for (int p = 0; p < 4; p++) {
                int idx = tid + p * 128;
                int row = idx >> 3, ch = idx & 7;
                uint32_t doff = row * 128 + ((uint32_t)(ch ^ (row & 7)) << 4);
                CP_ASYNC16(sK + doff, kp + (size_t)row * kDim + ch * 8);
                CP_ASYNC16(sV + doff, vp + (size_t)row * kDim + ch * 8);
            }
            CP_COMMIT();
            asm volatile("cp.async.wait_group 1;");
        } else {
            asm volatile("cp.async.wait_group 0;");
        }
        __syncthreads();

        if (t == 0) {
            #pragma unroll
            for (int ks = 0; ks < 4; ks++) {
                int row = w * 16 + (lane & 15);
                int ch  = ks * 2 + (lane >> 4);
                uint32_t addr = sQ + row * 128 + ((uint32_t)(ch ^ (row & 7)) << 4);
                LDSM4(qa[ks][0], qa[ks][1], qa[ks][2], qa[ks][3], addr);
            }
        }

        uint32_t sK = sQ + 8192 + s * 16384;
        uint32_t sV = sK + 8192;

        // S = Q K^T
        float sacc[8][4];
        #pragma unroll
        for (int j = 0; j < 8; j++)
            #pragma unroll
            for (int c = 0; c < 4; c++) sacc[j][c] = 0.f;

        #pragma unroll
        for (int ks = 0; ks < 4; ks++) {
            uint32_t bfr[8][2];
            #pragma unroll
            for (int ib = 0; ib < 4; ib++) {
                int row = ib * 16 + ((lane >> 4) << 3) + (lane & 7);
                int ch  = ks * 2 + ((lane >> 3) & 1);
                uint32_t addr = sK + row * 128 + ((uint32_t)(ch ^ (row & 7)) << 4);
                uint32_t r0, r1, r2, r3;
                LDSM4(r0, r1, r2, r3, addr);
                bfr[2*ib][0] = r0; bfr[2*ib][1] = r1;
                bfr[2*ib+1][0] = r2; bfr[2*ib+1][1] = r3;
            }
            #pragma unroll
            for (int j = 0; j < 8; j++)
                MMA16816(sacc[j], qa[ks][0], qa[ks][1], qa[ks][2], qa[ks][3],
                         bfr[j][0], bfr[j][1]);
        }

        // online softmax (scores * 0.5 = /TAU)
        float m0 = -1e30f, m1 = -1e30f;
        #pragma unroll
        for (int j = 0; j < 8; j++) {
            sacc[j][0] *= 0.5f; sacc[j][1] *= 0.5f;
            sacc[j][2] *= 0.5f; sacc[j][3] *= 0.5f;
            m0 = fmaxf(m0, fmaxf(sacc[j][0], sacc[j][1]));
            m1 = fmaxf(m1, fmaxf(sacc[j][2], sacc[j][3]));
        }
        m0 = fmaxf(m0, __shfl_xor_sync(0xffffffffu, m0, 1));
        m0 = fmaxf(m0, __shfl_xor_sync(0xffffffffu, m0, 2));
        m1 = fmaxf(m1, __shfl_xor_sync(0xffffffffu, m1, 1));
        m1 = fmaxf(m1, __shfl_xor_sync(0xffffffffu, m1, 2));
        float nm0 = fmaxf(mrow[0], m0), nm1 = fmaxf(mrow[1], m1);
        float sc0 = __expf(mrow[0] - nm0), sc1 = __expf(mrow[1] - nm1);
        mrow[0] = nm0; mrow[1] = nm1;

        float ps0 = 0.f, ps1 = 0.f;
        #pragma unroll
        for (int j = 0; j < 8; j++) {
            sacc[j][0] = __expf(sacc[j][0] - nm0);
            sacc[j][1] = __expf(sacc[j][1] - nm0);
            sacc[j][2] = __expf(sacc[j][2] - nm1);
            sacc[j][3] = __expf(sacc[j][3] - nm1);
            ps0 += sacc[j][0] + sacc[j][1];
            ps1 += sacc[j][2] + sacc[j][3];
        }
        lrow[0] = lrow[0] * sc0 + ps0;   // thread-partial; quad-reduced at end
        lrow[1] = lrow[1] * sc1 + ps1;
        #pragma unroll
        for (int j = 0; j < 8; j++) {
            oacc[j][0] *= sc0; oacc[j][1] *= sc0;
            oacc[j][2] *= sc1; oacc[j][3] *= sc1;
        }

        // P (C-frag) -> A-frag bf16
        uint32_t pa[4][4];
        #pragma unroll
        for (int kc = 0; kc < 4; kc++) {
            pa[kc][0] = pack_bf16(sacc[2*kc][0],   sacc[2*kc][1]);
            pa[kc][1] = pack_bf16(sacc[2*kc][2],   sacc[2*kc][3]);
            pa[kc][2] = pack_bf16(sacc[2*kc+1][0], sacc[2*kc+1][1]);
            pa[kc][3] = pack_bf16(sacc[2*kc+1][2], sacc[2*kc+1][3]);
        }

        // O += P V  (V^T frags via ldmatrix.trans)
        const int mi = lane >> 3;
        #pragma unroll
        for (int kc = 0; kc < 4; kc++) {
            #pragma unroll
            for (int ng = 0; ng < 4; ng++) {
                int row = kc * 16 + ((mi & 1) << 3) + (lane & 7);
                int ch  = ng * 2 + (mi >> 1);
                uint32_t addr = sV + row * 128 + ((uint32_t)(ch ^ (row & 7)) << 4);
                uint32_t r0, r1, r2, r3;
                LDSM4T(r0, r1, r2, r3, addr);
                MMA16816(oacc[2*ng],   pa[kc][0], pa[kc][1], pa[kc][2], pa[kc][3], r0, r1);
                MMA16816(oacc[2*ng+1], pa[kc][0], pa[kc][1], pa[kc][2], pa[kc][3], r2, r3);
            }
        }
        __syncthreads();
    }

    // finalize
    lrow[0] += __shfl_xor_sync(0xffffffffu, lrow[0], 1);
    lrow[0] += __shfl_xor_sync(0xffffffffu, lrow[0], 2);
    lrow[1] += __shfl_xor_sync(0xffffffffu, lrow[1], 1);
    lrow[1] += __shfl_xor_sync(0xffffffffu, lrow[1], 2);
    float inv0 = 1.0f / lrow[0], inv1 = 1.0f / lrow[1];

    const int g = lane >> 2, tg = lane & 3;
    size_t r0 = (size_t)(b * kLq + q0 + w * 16 + g) * kDim + h * 64;
    #pragma unroll
    for (int j = 0; j < 8; j++) {
        int c = j * 8 + tg * 2;
        *reinterpret_cast<__nv_bfloat162*>(&ctx[r0 + c]) =
            __floats2bfloat162_rn(oacc[j][0] * inv0, oacc[j][1] * inv0);
        *reinterpret_cast<__nv_bfloat162*>(&ctx[r0 + 8 * kDim + c]) =
            __floats2bfloat162_rn(oacc[j][2] * inv1, oacc[j][3] * inv1);
    }
}

// ---------------------------------------------------------------------------
// kernel_launch
// ---------------------------------------------------------------------------
extern "C" void kernel_launch(void* const* d_in, const int* in_sizes, int n_in,
                              void* d_out, int out_size)
{
    const float* q_tokens   = (const float*)d_in[0];
    const float* kv_tokens  = (const float*)d_in[1];
    const float* q_ln_w     = (const float*)d_in[2];
    const float* q_ln_b     = (const float*)d_in[3];
    const float* kv_ln_w    = (const float*)d_in[4];
    const float* kv_ln_b    = (const float*)d_in[5];
    const float* mlp_ln_w   = (const float*)d_in[6];
    const float* mlp_ln_b   = (const float*)d_in[7];
    const float* Wq         = (const float*)d_in[8];
    const float* Wk         = (const float*)d_in[9];
    const float* Wv         = (const float*)d_in[10];
    const float* Wo         = (const float*)d_in[11];
    const float* bo         = (const float*)d_in[12];
    const float* fc1_w      = (const float*)d_in[13];
    const float* fc1_b      = (const float*)d_in[14];
    const float* fc2_w      = (const float*)d_in[15];
    const float* fc2_b      = (const float*)d_in[16];
    const float* alpha_attn = (const float*)d_in[17];
    const float* alpha_mlp  = (const float*)d_in[18];
    float* out = (float*)d_out;

    unsigned char* arena = nullptr;
    cudaGetSymbolAddress((void**)&arena, g_scratch);
    const size_t MB = 1024u * 1024u;

    __nv_bfloat16* qn   = (__nv_bfloat16*)(arena + 0 * MB);
    __nv_bfloat16* kvn  = (__nv_bfloat16*)(arena + 4 * MB);
    __nv_bfloat16* Wqb  = (__nv_bfloat16*)(arena + 20 * MB);
    __nv_bfloat16* Wkb  = (__nv_bfloat16*)(arena + 22 * MB);
    __nv_bfloat16* Wvb  = (__nv_bfloat16*)(arena + 24 * MB);
    __nv_bfloat16* Wob  = (__nv_bfloat16*)(arena + 26 * MB);
    __nv_bfloat16* fc1b = (__nv_bfloat16*)(arena + 28 * MB);
    __nv_bfloat16* fc2b = (__nv_bfloat16*)(arena + 36 * MB);
    __nv_bfloat16* qb   = (__nv_bfloat16*)(arena + 44 * MB);   // 4 MB
    __nv_bfloat16* kb   = (__nv_bfloat16*)(arena + 48 * MB);   // 16 MB
    __nv_bfloat16* vb   = (__nv_bfloat16*)(arena + 64 * MB);   // 16 MB
    __nv_bfloat16* ctxb = (__nv_bfloat16*)(arena + 80 * MB);   // 4 MB
    __nv_bfloat16* hln  = (__nv_bfloat16*)(arena + 84 * MB);   // 4 MB
    __nv_bfloat16* h1b  = (__nv_bfloat16*)(arena + 88 * MB);   // 16 MB

    cudaFuncSetAttribute(gemm_bf16_kernel<1>, cudaFuncAttributeMaxDynamicSharedMemorySize, 65536);
    cudaFuncSetAttribute(gemm_bf16_kernel<2>, cudaFuncAttributeMaxDynamicSharedMemorySize, 65536);
    cudaFuncSetAttribute(gemm_bf16_kernel<3>, cudaFuncAttributeMaxDynamicSharedMemorySize, 65536);
    cudaFuncSetAttribute(gemm_bf16_kernel<4>, cudaFuncAttributeMaxDynamicSharedMemorySize, 65536);

    cvt_bf16_kernel<<<(kDim * kDim) / 1024, 256>>>(Wq, Wqb, kDim * kDim);
    cvt_bf16_kernel<<<(kDim * kDim) / 1024, 256>>>(Wk, Wkb, kDim * kDim);
    cvt_bf16_kernel<<<(kDim * kDim) / 1024, 256>>>(Wv, Wvb, kDim * kDim);
    cvt_bf16_kernel<<<(kDim * kDim) / 1024, 256>>>(Wo, Wob, kDim * kDim);
    cvt_bf16_kernel<<<(kMlp * kDim) / 1024, 256>>>(fc1_w, fc1b, kMlp * kDim);
    cvt_bf16_kernel<<<(kMlp * kDim) / 1024, 256>>>(fc2_w, fc2b, kMlp * kDim);

    ln_bf16_kernel<<<kNQ, 256>>>(q_tokens, q_ln_w, q_ln_b, qn);
    ln_bf16_kernel<<<kNKV, 256>>>(kv_tokens, kv_ln_w, kv_ln_b, kvn);

    // projections: Q,K with fused per-head l2norm; V plain (all bf16 out)
    gemm_bf16_kernel<3><<<dim3(kDim / 128, kNQ / 128), 256, 65536>>>(
        qn, Wqb, kNQ, kDim, kDim, nullptr, nullptr, nullptr, nullptr, qb);
    gemm_bf16_kernel<3><<<dim3(kDim / 128, kNKV / 128), 256, 65536>>>(
        kvn, Wkb, kNKV, kDim, kDim, nullptr, nullptr, nullptr, nullptr, kb);
    gemm_bf16_kernel<4><<<dim3(kDim / 128, kNKV / 128), 256, 65536>>>(
        kvn, Wvb, kNKV, kDim, kDim, nullptr, nullptr, nullptr, nullptr, vb);

    attn_mma_kernel<<<dim3(kB * kH, kLq / 64), 128>>>(qb, kb, vb, ctxb);

    // out = q_tokens + alpha_attn * (ctx @ Wo^T + bo)
    gemm_bf16_kernel<2><<<dim3(kDim / 128, kNQ / 128), 256, 65536>>>(
        ctxb, Wob, kNQ, kDim, kDim, bo, q_tokens, alpha_attn, out, nullptr);

    ln_bf16_kernel<<<kNQ, 256>>>(out, mlp_ln_w, mlp_ln_b, hln);

    gemm_bf16_kernel<1><<<dim3(kMlp / 128, kNQ / 128), 256, 65536>>>(
        hln, fc1b, kNQ, kMlp, kDim, fc1_b, nullptr, nullptr, nullptr, h1b);

    gemm_bf16_kernel<2><<<dim3(kDim / 128, kNQ / 128), 256, 65536>>>(
        h1b, fc2b, kNQ, kDim, kMlp, fc2_b, out, alpha_mlp, out, nullptr);
}